// round 1
// baseline (speedup 1.0000x reference)
#include <cuda_runtime.h>
#include <math.h>

#define BB 64
#define NN 256
#define DD 64
#define TT 4096
#define TCHUNKS 16
#define TPB 256       // threads per block == tasks per chunk
#define NCHUNK 8

// Scratch: per (b, tchunk, n): (m, s, p, pad). 64*16*256*16B = 4 MB.
__device__ float4 g_scratch[BB * TCHUNKS * NN];
__device__ float  g_wmean[DD];

// ---------------------------------------------------------------------------
// Kernel 0: column means of W (== row means over t of task_pool[t][d])
// ---------------------------------------------------------------------------
__global__ void wmean_kernel(const float* __restrict__ W) {
    __shared__ float part[4][DD];
    int d = threadIdx.x & 63;
    int g = threadIdx.x >> 6;
    float s = 0.f;
    for (int t = g; t < TT; t += 4)
        s += W[(size_t)t * DD + d];
    part[g][d] = s;
    __syncthreads();
    if (threadIdx.x < DD) {
        float tot = part[0][d] + part[1][d] + part[2][d] + part[3][d];
        g_wmean[d] = tot * (1.0f / (float)TT);
    }
}

// ---------------------------------------------------------------------------
// Kernel 1: fused Z-GEMM + cumulative log-lik + online softmax partials
// grid (TCHUNKS, B), 256 threads. Thread owns task t = blockIdx.x*256 + tid.
// ---------------------------------------------------------------------------
__global__ void __launch_bounds__(TPB, 2)
main_kernel(const float* __restrict__ data,
            const float* __restrict__ targets,
            const float* __restrict__ W) {
    const int tc   = blockIdx.x;
    const int b    = blockIdx.y;
    const int tid  = threadIdx.x;
    const int wid  = tid >> 5;
    const int lane = tid & 31;
    const int t    = tc * TPB + tid;

    __shared__ float4 sd4[NCHUNK * DD / 4];   // 8 data rows (2 KB)
    __shared__ float  st[NCHUNK];
    __shared__ float  redm[NCHUNK][8];
    __shared__ float  reds[NCHUNK][8];
    __shared__ float  redp[NCHUNK][8];

    // W column for this task: 64 contiguous floats of task_pool[t]
    float w[DD];
    const float4* wp = (const float4*)(W + (size_t)t * DD);
    #pragma unroll
    for (int k = 0; k < DD / 4; k++) {
        float4 v = wp[k];
        w[4*k+0] = v.x; w[4*k+1] = v.y; w[4*k+2] = v.z; w[4*k+3] = v.w;
    }

    const float* db = data    + (size_t)b * NN * DD;
    const float* tb = targets + (size_t)b * NN;
    float* sdf = (float*)sd4;

    float cum = 0.f;
    for (int c = 0; c < NN / NCHUNK; c++) {
        __syncthreads();   // protects sd4/st/red* from previous chunk
        sdf[tid]       = db[c * (NCHUNK * DD) + tid];
        sdf[tid + 256] = db[c * (NCHUNK * DD) + tid + 256];
        if (tid < NCHUNK) st[tid] = tb[c * NCHUNK + tid];
        __syncthreads();

        float cv[NCHUNK], zv[NCHUNK];
        #pragma unroll
        for (int j = 0; j < NCHUNK; j++) {
            cv[j] = cum;                       // alphas value for step n
            float z = 0.f;
            const float4* dr = sd4 + j * (DD / 4);
            #pragma unroll
            for (int k = 0; k < DD / 4; k++) {
                float4 v = dr[k];              // LDS broadcast
                z = fmaf(v.x, w[4*k+0], z);
                z = fmaf(v.y, w[4*k+1], z);
                z = fmaf(v.z, w[4*k+2], z);
                z = fmaf(v.w, w[4*k+3], z);
            }
            zv[j] = z;
            float r = st[j] - z;
            cum = fmaf(-0.5f * r, r, cum);     // += logpdf (const dropped)
        }

        // --- batched block max over t for the 8 steps ---
        #pragma unroll
        for (int j = 0; j < NCHUNK; j++) {
            float m = cv[j];
            #pragma unroll
            for (int o = 16; o > 0; o >>= 1)
                m = fmaxf(m, __shfl_xor_sync(0xffffffffu, m, o));
            if (lane == 0) redm[j][wid] = m;
        }
        __syncthreads();
        float bm[NCHUNK];
        #pragma unroll
        for (int j = 0; j < NCHUNK; j++) {
            float m = redm[j][0];
            #pragma unroll
            for (int q = 1; q < 8; q++) m = fmaxf(m, redm[j][q]);
            bm[j] = m;
        }

        // --- exp + batched sum reductions (s = Σe, p = Σ e·z) ---
        #pragma unroll
        for (int j = 0; j < NCHUNK; j++) {
            float e = __expf(cv[j] - bm[j]);
            float p = e * zv[j];
            #pragma unroll
            for (int o = 16; o > 0; o >>= 1) {
                e += __shfl_xor_sync(0xffffffffu, e, o);
                p += __shfl_xor_sync(0xffffffffu, p, o);
            }
            if (lane == 0) { reds[j][wid] = e; redp[j][wid] = p; }
        }
        __syncthreads();

        if (wid == 0 && lane < NCHUNK) {
            const int j = lane;
            float s = 0.f, p = 0.f;
            #pragma unroll
            for (int q = 0; q < 8; q++) { s += reds[j][q]; p += redp[j][q]; }
            const int n = c * NCHUNK + j;
            g_scratch[((size_t)b * TCHUNKS + tc) * NN + n] =
                make_float4(bm[j], s, p, 0.f);
        }
    }
}

// ---------------------------------------------------------------------------
// Kernel 2: merge the 16 t-chunk partials per (b, n); handle n==0 (pred0).
// grid B, 256 threads.
// ---------------------------------------------------------------------------
__global__ void merge_kernel(const float* __restrict__ data,
                             float* __restrict__ out) {
    const int b = blockIdx.x;
    const int n = threadIdx.x;
    if (n == 0) {
        float s = 0.f;
        const float* d0 = data + (size_t)b * NN * DD;
        #pragma unroll
        for (int d = 0; d < DD; d++) s = fmaf(d0[d], g_wmean[d], s);
        out[(size_t)b * NN] = s;
        return;
    }
    const float4* base = &g_scratch[(size_t)b * TCHUNKS * NN + n];
    float4 v[TCHUNKS];
    float M = -INFINITY;
    #pragma unroll
    for (int k = 0; k < TCHUNKS; k++) {
        v[k] = base[(size_t)k * NN];
        M = fmaxf(M, v[k].x);
    }
    float S = 0.f, P = 0.f;
    #pragma unroll
    for (int k = 0; k < TCHUNKS; k++) {
        float sc = __expf(v[k].x - M);
        S = fmaf(v[k].y, sc, S);
        P = fmaf(v[k].z, sc, P);
    }
    out[(size_t)b * NN + n] = P / S;
}

// ---------------------------------------------------------------------------
extern "C" void kernel_launch(void* const* d_in, const int* in_sizes, int n_in,
                              void* d_out, int out_size) {
    const float* data    = (const float*)d_in[0];   // (64,256,64)
    const float* targets = (const float*)d_in[1];   // (64,256)
    const float* W       = (const float*)d_in[2];   // (4096,64,1)
    float* out = (float*)d_out;                     // (64,256)

    wmean_kernel<<<1, 256>>>(W);
    main_kernel<<<dim3(TCHUNKS, BB), TPB>>>(data, targets, W);
    merge_kernel<<<BB, NN>>>(data, out);
}

// round 2
// speedup vs baseline: 1.2708x; 1.2708x over previous
#include <cuda_runtime.h>
#include <math.h>
#include <stdint.h>

#define BB 64
#define NN 256
#define DD 64
#define TT 4096
#define TPB 256
#define TCH 16                 // t-chunks (TT / TPB)
#define NCH 8                  // n-steps per chunk
#define NCHUNKS (NN / NCH)     // 32
#define KREC 128               // TCH * 8 warps of partials per (b,n)

// Per-(b, k=tc*8+wid, n) softmax partials: (max, sum_e, sum_e*z, pad). 32 MB.
__device__ float4 g_scratch[(size_t)BB * KREC * NN];

#define FMA2(d, a, b, c) \
    asm("fma.rn.f32x2 %0, %1, %2, %3;" : "=l"(d) : "l"(a), "l"(b), "l"(c))

// ---------------------------------------------------------------------------
// Main kernel: fused Z-GEMM (packed f32x2) + cumulative loglik + per-warp
// online-softmax partials. grid (TCH, BB), 256 threads; thread owns task t.
// ---------------------------------------------------------------------------
__global__ void __launch_bounds__(TPB, 2)
main_kernel(const float* __restrict__ data,
            const float* __restrict__ targets,
            const float* __restrict__ W)
{
    const int tc   = blockIdx.x;
    const int b    = blockIdx.y;
    const int tid  = threadIdx.x;
    const int wid  = tid >> 5;
    const int lane = tid & 31;
    const int t    = tc * TPB + tid;

    __shared__ float sdf[2][NCH * DD];   // double-buffered 8 data rows (2x2KB)
    __shared__ float st[2][NCH];         // targets for the chunk

    // W column for this task, kept as 32 packed f32x2 (even/odd d pairs).
    unsigned long long w2[DD / 2];
    {
        const unsigned long long* wp =
            (const unsigned long long*)(W + (size_t)t * DD);
        #pragma unroll
        for (int k = 0; k < DD / 2; k++) w2[k] = wp[k];
    }

    uint32_t sbase;
    asm("{ .reg .u64 tt; cvta.to.shared.u64 tt, %1; cvt.u32.u64 %0, tt; }"
        : "=r"(sbase) : "l"(&sdf[0][0]));

    const float* db = data    + (size_t)b * NN * DD;
    const float* tb = targets + (size_t)b * NN;

    // Preload chunk 0
    sdf[0][tid]       = db[tid];
    sdf[0][tid + 256] = db[tid + 256];
    if (tid < NCH) st[0][tid] = tb[tid];
    __syncthreads();

    float cum = 0.f;
    float4* srec = &g_scratch[((size_t)b * KREC + (tc * 8 + wid)) * NN];

    for (int c = 0; c < NCHUNKS; c++) {
        const int cur = c & 1, nxt = cur ^ 1;

        // Prefetch next chunk into registers (hidden under compute)
        float r0 = 0.f, r1 = 0.f, rt = 0.f;
        const bool has = (c + 1 < NCHUNKS);
        if (has) {
            const float* g = db + (c + 1) * (NCH * DD);
            r0 = g[tid];
            r1 = g[tid + 256];
            if (tid < NCH) rt = tb[(c + 1) * NCH + tid];
        }

        // ---- Z GEMM for 8 steps, packed over d (even/odd) ----
        unsigned long long acc[NCH];
        #pragma unroll
        for (int j = 0; j < NCH; j++) acc[j] = 0ULL;

        const uint32_t cb = sbase + cur * (NCH * DD * 4);
        #pragma unroll
        for (int kk = 0; kk < 16; kk++) {
            #pragma unroll
            for (int j = 0; j < NCH; j++) {
                unsigned long long v0, v1;
                asm("ld.shared.v2.b64 {%0,%1}, [%2];"
                    : "=l"(v0), "=l"(v1)
                    : "r"(cb + j * (DD * 4) + kk * 16));
                FMA2(acc[j], v0, w2[2 * kk],     acc[j]);
                FMA2(acc[j], v1, w2[2 * kk + 1], acc[j]);
            }
        }

        float z[NCH], cv[NCH];
        #pragma unroll
        for (int j = 0; j < NCH; j++) {
            uint32_t lo, hi;
            asm("mov.b64 {%0,%1}, %2;" : "=r"(lo), "=r"(hi) : "l"(acc[j]));
            z[j] = __uint_as_float(lo) + __uint_as_float(hi);
        }

        // ---- cumulative log-lik (constant term cancels in softmax) ----
        #pragma unroll
        for (int j = 0; j < NCH; j++) {
            cv[j] = cum;                       // alphas for output step c*8+j
            float r = st[cur][j] - z[j];
            cum = fmaf(r * -0.5f, r, cum);
        }

        // ---- per-warp max over the 32 tasks, per step ----
        float m[NCH];
        #pragma unroll
        for (int j = 0; j < NCH; j++) {
            float v = cv[j];
            #pragma unroll
            for (int o = 16; o > 0; o >>= 1)
                v = fmaxf(v, __shfl_xor_sync(0xffffffffu, v, o));
            m[j] = v;
        }

        // ---- exp + per-warp sums; route step j's result to lane j ----
        float msel = 0.f, ssel = 0.f, psel = 0.f;
        #pragma unroll
        for (int j = 0; j < NCH; j++) {
            float e = __expf(cv[j] - m[j]);
            float p = e * z[j];
            #pragma unroll
            for (int o = 16; o > 0; o >>= 1) {
                e += __shfl_xor_sync(0xffffffffu, e, o);
                p += __shfl_xor_sync(0xffffffffu, p, o);
            }
            if (j == 0)          { msel = m[0]; ssel = e; psel = p; }
            else if (lane == j)  { msel = m[j]; ssel = e; psel = p; }
        }
        if (lane < NCH)
            srec[c * NCH + lane] = make_float4(msel, ssel, psel, 0.f);

        // ---- stage next chunk ----
        if (has) {
            sdf[nxt][tid]       = r0;
            sdf[nxt][tid + 256] = r1;
            if (tid < NCH) st[nxt][tid] = rt;
        }
        __syncthreads();
    }
}

// ---------------------------------------------------------------------------
// Merge: combine 128 per-warp partials per (b, n) via stable softmax algebra.
// n=0 needs no special case: all partial maxes are 0 there, so the result is
// the uniform-weight mean of Z[b,0,:], which equals data[b,0] @ W.mean(axis=1).
// ---------------------------------------------------------------------------
__global__ void merge_kernel(float* __restrict__ out)
{
    const int b = blockIdx.x;
    const int n = threadIdx.x;
    const float4* base = &g_scratch[(size_t)b * KREC * NN + n];

    float M = -3.4e38f;
    #pragma unroll 8
    for (int k = 0; k < KREC; k++)
        M = fmaxf(M, __ldg(&base[(size_t)k * NN]).x);

    float S = 0.f, P = 0.f;
    #pragma unroll 8
    for (int k = 0; k < KREC; k++) {
        float4 v = __ldg(&base[(size_t)k * NN]);
        float e = __expf(v.x - M);
        S = fmaf(v.y, e, S);
        P = fmaf(v.z, e, P);
    }
    out[(size_t)b * NN + n] = P / S;
}

// ---------------------------------------------------------------------------
extern "C" void kernel_launch(void* const* d_in, const int* in_sizes, int n_in,
                              void* d_out, int out_size)
{
    const float* data    = (const float*)d_in[0];   // (64, 256, 64)
    const float* targets = (const float*)d_in[1];   // (64, 256)
    const float* W       = (const float*)d_in[2];   // (4096, 64, 1)
    float* out = (float*)d_out;                     // (64, 256)

    main_kernel<<<dim3(TCH, BB), TPB>>>(data, targets, W);
    merge_kernel<<<BB, NN>>>(out);
}

// round 3
// speedup vs baseline: 1.5823x; 1.2450x over previous
#include <cuda_runtime.h>
#include <math.h>
#include <stdint.h>

#define BB 64
#define NN 256
#define DD 64
#define TT 4096
#define TPB 128                // threads per block (4 warps)
#define WPB 4
#define TCH (TT / TPB)         // 32 t-chunks
#define NCH 8                  // n-steps per chunk
#define NCHUNKS (NN / NCH)     // 32
#define KREC (TCH * WPB)       // 128 warp partials per (b,n)

// Per-(b, k, n) softmax partials: (max, sum_e, sum_e*z, pad). 32 MB.
__device__ float4 g_scratch[(size_t)BB * KREC * NN];

#define FMA2(d, a, b, c) \
    asm("fma.rn.f32x2 %0, %1, %2, %3;" : "=l"(d) : "l"(a), "l"(b), "l"(c))

// Monotone float<->uint order map (for integer max-reduce of floats)
__device__ __forceinline__ unsigned fkey(float x) {
    unsigned u = __float_as_uint(x);
    return (u & 0x80000000u) ? ~u : (u | 0x80000000u);
}
__device__ __forceinline__ float finv(unsigned k) {
    unsigned u = (k & 0x80000000u) ? (k ^ 0x80000000u) : ~k;
    return __uint_as_float(u);
}

// ---------------------------------------------------------------------------
// Main kernel: fused Z-GEMM (packed f32x2) + cumulative loglik + per-warp
// online-softmax partials via REDUX. grid (TCH, BB), 128 threads.
// ---------------------------------------------------------------------------
__global__ void __launch_bounds__(TPB, 4)
main_kernel(const float* __restrict__ data,
            const float* __restrict__ targets,
            const float* __restrict__ W)
{
    const int tc   = blockIdx.x;
    const int b    = blockIdx.y;
    const int tid  = threadIdx.x;
    const int wid  = tid >> 5;
    const int lane = tid & 31;
    const int t    = tc * TPB + tid;

    __shared__ float sdf[2][NCH * DD];   // double-buffered 8 data rows
    __shared__ float st[2][NCH];

    // W column for this task, packed f32x2 over d.
    unsigned long long w2[DD / 2];
    {
        const unsigned long long* wp =
            (const unsigned long long*)(W + (size_t)t * DD);
        #pragma unroll
        for (int k = 0; k < DD / 2; k++) w2[k] = wp[k];
    }

    uint32_t sbase;
    asm("{ .reg .u64 tt; cvta.to.shared.u64 tt, %1; cvt.u32.u64 %0, tt; }"
        : "=r"(sbase) : "l"(&sdf[0][0]));

    const float* db = data    + (size_t)b * NN * DD;
    const float* tb = targets + (size_t)b * NN;

    // Preload chunk 0
    #pragma unroll
    for (int k = 0; k < 4; k++) sdf[0][tid + k * TPB] = db[tid + k * TPB];
    if (tid < NCH) st[0][tid] = tb[tid];
    __syncthreads();

    float cum = 0.f;
    float4* srec = &g_scratch[((size_t)b * KREC + (tc * WPB + wid)) * NN];

    for (int c = 0; c < NCHUNKS; c++) {
        const int cur = c & 1, nxt = cur ^ 1;

        // Prefetch next chunk into registers
        float r[4], rt = 0.f;
        const bool has = (c + 1 < NCHUNKS);
        if (has) {
            const float* g = db + (c + 1) * (NCH * DD);
            #pragma unroll
            for (int k = 0; k < 4; k++) r[k] = g[tid + k * TPB];
            if (tid < NCH) rt = tb[(c + 1) * NCH + tid];
        }

        // ---- Z GEMM for 8 steps, packed over d (even/odd) ----
        unsigned long long acc[NCH];
        #pragma unroll
        for (int j = 0; j < NCH; j++) acc[j] = 0ULL;

        const uint32_t cb = sbase + cur * (NCH * DD * 4);
        #pragma unroll
        for (int kk = 0; kk < 16; kk++) {
            #pragma unroll
            for (int j = 0; j < NCH; j++) {
                unsigned long long v0, v1;
                asm("ld.shared.v2.b64 {%0,%1}, [%2];"
                    : "=l"(v0), "=l"(v1)
                    : "r"(cb + j * (DD * 4) + kk * 16));
                FMA2(acc[j], v0, w2[2 * kk],     acc[j]);
                FMA2(acc[j], v1, w2[2 * kk + 1], acc[j]);
            }
        }

        float z[NCH], cv[NCH];
        #pragma unroll
        for (int j = 0; j < NCH; j++) {
            uint32_t lo, hi;
            asm("mov.b64 {%0,%1}, %2;" : "=r"(lo), "=r"(hi) : "l"(acc[j]));
            z[j] = __uint_as_float(lo) + __uint_as_float(hi);
        }
        #pragma unroll
        for (int j = 0; j < NCH; j++) {
            cv[j] = cum;                       // weights for output step c*8+j
            float rr = st[cur][j] - z[j];
            cum = fmaf(rr * -0.5f, rr, cum);
        }

        // ---- per-step warp softmax partials via REDUX ----
        float msel = 0.f, ssel = 0.f, psel = 0.f;
        #pragma unroll
        for (int j = 0; j < NCH; j++) {
            unsigned km = __reduce_max_sync(0xffffffffu, fkey(cv[j]));
            float m = finv(km);
            float e = __expf(cv[j] - m);       // in (0,1], max lane == 1
            int ie = __float2int_rn(e * 16777216.0f);           // 2^24
            int ip = __float2int_rn(e * z[j] * 131072.0f);      // 2^17
            int se = __reduce_add_sync(0xffffffffu, ie);
            int sp = __reduce_add_sync(0xffffffffu, ip);
            if (lane == j) {
                msel = m;
                ssel = (float)se * 5.9604644775390625e-8f;      // 2^-24
                psel = (float)sp * 7.62939453125e-6f;           // 2^-17
            }
        }
        if (lane < NCH)
            srec[c * NCH + lane] = make_float4(msel, ssel, psel, 0.f);

        // ---- stage next chunk ----
        if (has) {
            #pragma unroll
            for (int k = 0; k < 4; k++) sdf[nxt][tid + k * TPB] = r[k];
            if (tid < NCH) st[nxt][tid] = rt;
        }
        __syncthreads();
    }
}

// ---------------------------------------------------------------------------
// Merge: 4 threads per (b,n), each covers 32 of the 128 partials, two-pass
// (max, then rescaled sums), combined with 2-level shuffles.
// grid 256 blocks x 256 threads. n==0 falls out naturally (all m==0, uniform).
// ---------------------------------------------------------------------------
__global__ void __launch_bounds__(256)
merge_kernel(float* __restrict__ out)
{
    const int gp = blockIdx.x * 64 + (threadIdx.x >> 2);  // (b,n) pair id
    const int q  = threadIdx.x & 3;
    const int b  = gp >> 8;
    const int n  = gp & 255;
    const float4* base = &g_scratch[(size_t)b * KREC * NN + n];

    // pass 1: local max over k = q, q+4, ..., q+124
    float M = -3.4e38f;
    #pragma unroll 8
    for (int i = 0; i < 32; i++)
        M = fmaxf(M, __ldg(&base[(size_t)(q + 4 * i) * NN]).x);

    // group max (lanes q^1, q^2 within the same 4-lane group)
    float gM = M;
    gM = fmaxf(gM, __shfl_xor_sync(0xffffffffu, gM, 1));
    gM = fmaxf(gM, __shfl_xor_sync(0xffffffffu, gM, 2));

    // pass 2: sums rescaled to group max (L2-resident reload)
    float S = 0.f, P = 0.f;
    #pragma unroll 8
    for (int i = 0; i < 32; i++) {
        float4 v = __ldg(&base[(size_t)(q + 4 * i) * NN]);
        float e = __expf(v.x - gM);
        S = fmaf(v.y, e, S);
        P = fmaf(v.z, e, P);
    }
    S += __shfl_xor_sync(0xffffffffu, S, 1);
    P += __shfl_xor_sync(0xffffffffu, P, 1);
    S += __shfl_xor_sync(0xffffffffu, S, 2);
    P += __shfl_xor_sync(0xffffffffu, P, 2);

    if (q == 0)
        out[(size_t)b * NN + n] = P / S;
}

// ---------------------------------------------------------------------------
extern "C" void kernel_launch(void* const* d_in, const int* in_sizes, int n_in,
                              void* d_out, int out_size)
{
    const float* data    = (const float*)d_in[0];   // (64, 256, 64)
    const float* targets = (const float*)d_in[1];   // (64, 256)
    const float* W       = (const float*)d_in[2];   // (4096, 64, 1)
    float* out = (float*)d_out;                     // (64, 256)

    main_kernel<<<dim3(TCH, BB), TPB>>>(data, targets, W);
    merge_kernel<<<256, 256>>>(out);
}

// round 4
// speedup vs baseline: 2.0995x; 1.3269x over previous
#include <cuda_runtime.h>
#include <math.h>
#include <stdint.h>

#define BB 64
#define NN 256
#define DD 64
#define TT 4096
#define TPB 128
#define WPB 4
#define TASKS_PER_BLOCK 256        // 2 tasks per thread
#define TCH (TT / TASKS_PER_BLOCK) // 16
#define NCH 16                     // n-steps per chunk
#define NCHUNKS (NN / NCH)         // 16
#define KREC (TCH * WPB)           // 64 warp-partials per (b,n)

// smem layout (dynamic):
//  [0, 64K)        W tile: 256 rows x 256B, 16B chunk kk of row r stored at
//                  r*256 + ((kk ^ (r&15))<<4)  (conflict-free warp reads)
//  [64K, 72K)      data double buffer: 2 x (16 rows x 256B)
//  [72K, 73K)      targets (256 floats)
#define SM_W    0
#define SM_DATA (256 * 256)
#define SM_TGT  (SM_DATA + 2 * NCH * DD * 4)
#define SMEM_BYTES (SM_TGT + NN * 4)

// Per-(b, k, n) softmax partials: (max, sum_e, sum_e*z, pad). 16 MB.
__device__ float4 g_scratch[(size_t)BB * KREC * NN];

#define FMA2(d, a, b, c) \
    asm("fma.rn.f32x2 %0, %1, %2, %3;" : "=l"(d) : "l"(a), "l"(b), "l"(c))

__device__ __forceinline__ void cp16(uint32_t dst, const void* src) {
    asm volatile("cp.async.cg.shared.global [%0], [%1], 16;"
                 :: "r"(dst), "l"(src));
}
#define CP_COMMIT() asm volatile("cp.async.commit_group;")
#define CP_WAIT0()  asm volatile("cp.async.wait_group 0;" ::: "memory")

__device__ __forceinline__ unsigned fkey(float x) {
    unsigned u = __float_as_uint(x);
    return (u & 0x80000000u) ? ~u : (u | 0x80000000u);
}
__device__ __forceinline__ float finv(unsigned k) {
    unsigned u = (k & 0x80000000u) ? (k ^ 0x80000000u) : ~k;
    return __uint_as_float(u);
}

// ---------------------------------------------------------------------------
// Main kernel: smem-tiled W, 2 tasks/thread, fused Z-GEMM (f32x2) +
// cumulative loglik + per-warp softmax partials. grid (TCH, BB), 128 thr.
// ---------------------------------------------------------------------------
extern "C" __global__ void __launch_bounds__(TPB, 3)
main_kernel(const float* __restrict__ data,
            const float* __restrict__ targets,
            const float* __restrict__ W)
{
    extern __shared__ __align__(1024) char smem[];
    uint32_t sb;
    asm("{ .reg .u64 tt; cvta.to.shared.u64 tt, %1; cvt.u32.u64 %0, tt; }"
        : "=r"(sb) : "l"(smem));

    const int tc   = blockIdx.x;
    const int b    = blockIdx.y;
    const int tid  = threadIdx.x;
    const int wid  = tid >> 5;
    const int lane = tid & 31;

    const float* db = data    + (size_t)b * NN * DD;
    const float* tb = targets + (size_t)b * NN;
    const float* wt = W + (size_t)tc * TASKS_PER_BLOCK * DD;

    // ---- prologue: async-load W tile (swizzled), targets, data chunk 0 ----
    #pragma unroll
    for (int i = 0; i < 32; i++) {
        int idx = i * TPB + tid;         // 0..4095 (row, chunk) pairs
        int r  = idx >> 4;
        int kk = idx & 15;
        cp16(sb + SM_W + r * 256 + ((kk ^ (r & 15)) << 4),
             wt + (size_t)r * DD + kk * 4);
    }
    if (tid < 64) cp16(sb + SM_TGT + tid * 16, tb + tid * 4);
    cp16(sb + SM_DATA + tid * 32,      db + tid * 8);
    cp16(sb + SM_DATA + tid * 32 + 16, db + tid * 8 + 4);
    CP_COMMIT();
    CP_WAIT0();
    __syncthreads();

    const int s = tid & 15;                           // swizzle key
    const uint32_t wrow0 = sb + SM_W + tid * 256;     // task row tid
    const uint32_t wrow1 = wrow0 + 128 * 256;         // task row tid+128
    const uint32_t dbase = sb + SM_DATA;

    float cum0 = 0.f, cum1 = 0.f;
    float4* srec = &g_scratch[((size_t)b * KREC + (tc * WPB + wid)) * NN];

    for (int c = 0; c < NCHUNKS; c++) {
        const int cur = c & 1;

        // prefetch next data chunk via cp.async
        if (c + 1 < NCHUNKS) {
            const float* g = db + (c + 1) * (NCH * DD);
            uint32_t d = dbase + (cur ^ 1) * (NCH * DD * 4) + tid * 32;
            cp16(d,      g + tid * 8);
            cp16(d + 16, g + tid * 8 + 4);
        }
        CP_COMMIT();

        // ---- Z GEMM: 16 steps x 2 tasks, f32x2-packed over d ----
        unsigned long long acc0[NCH], acc1[NCH];
        #pragma unroll
        for (int j = 0; j < NCH; j++) { acc0[j] = 0ULL; acc1[j] = 0ULL; }

        const uint32_t cb = dbase + cur * (NCH * DD * 4);
        #pragma unroll 4
        for (int kk = 0; kk < 16; kk++) {
            const uint32_t woff = (uint32_t)((s ^ kk) << 4);
            unsigned long long w00, w01, w10, w11;
            asm("ld.shared.v2.b64 {%0,%1}, [%2];"
                : "=l"(w00), "=l"(w01) : "r"(wrow0 + woff));
            asm("ld.shared.v2.b64 {%0,%1}, [%2];"
                : "=l"(w10), "=l"(w11) : "r"(wrow1 + woff));
            #pragma unroll
            for (int j = 0; j < NCH; j++) {
                unsigned long long v0, v1;
                asm("ld.shared.v2.b64 {%0,%1}, [%2];"
                    : "=l"(v0), "=l"(v1)
                    : "r"(cb + j * (DD * 4) + kk * 16));
                FMA2(acc0[j], v0, w00, acc0[j]);
                FMA2(acc0[j], v1, w01, acc0[j]);
                FMA2(acc1[j], v0, w10, acc1[j]);
                FMA2(acc1[j], v1, w11, acc1[j]);
            }
        }

        // ---- epilogue: cum loglik + warp softmax partials (over 64 tasks) --
        const uint32_t tgta = sb + SM_TGT + c * (NCH * 4);
        float mO = 0.f, sO = 0.f, pO = 0.f;
        #pragma unroll
        for (int j = 0; j < NCH; j++) {
            uint32_t lo, hi;
            float z0, z1, tj;
            asm("mov.b64 {%0,%1}, %2;" : "=r"(lo), "=r"(hi) : "l"(acc0[j]));
            z0 = __uint_as_float(lo) + __uint_as_float(hi);
            asm("mov.b64 {%0,%1}, %2;" : "=r"(lo), "=r"(hi) : "l"(acc1[j]));
            z1 = __uint_as_float(lo) + __uint_as_float(hi);
            asm("ld.shared.f32 %0, [%1];" : "=f"(tj) : "r"(tgta + j * 4));

            float cv0 = cum0, cv1 = cum1;
            float r0 = tj - z0; cum0 = fmaf(r0 * -0.5f, r0, cum0);
            float r1 = tj - z1; cum1 = fmaf(r1 * -0.5f, r1, cum1);

            unsigned km = __reduce_max_sync(0xffffffffu, fkey(fmaxf(cv0, cv1)));
            float m  = finv(km);
            float e0 = __expf(cv0 - m);
            float e1 = __expf(cv1 - m);
            int ie = __float2int_rn((e0 + e1) * 16777216.0f);          // 2^24
            int ip = __float2int_rn(fmaf(e0, z0, e1 * z1) * 131072.0f); // 2^17
            int se = __reduce_add_sync(0xffffffffu, ie);
            int sp = __reduce_add_sync(0xffffffffu, ip);
            if (lane == j) {
                mO = m;
                sO = (float)se * 5.9604644775390625e-8f;  // 2^-24
                pO = (float)sp * 7.62939453125e-6f;       // 2^-17
            }
        }
        if (lane < NCH)
            srec[c * NCH + lane] = make_float4(mO, sO, pO, 0.f);

        CP_WAIT0();
        __syncthreads();
    }
}

// ---------------------------------------------------------------------------
// Merge: 4 threads per (b,n), 16 partials each; two-pass stable softmax.
// n==0 falls out naturally (all maxes 0 -> uniform weights -> pred0).
// ---------------------------------------------------------------------------
extern "C" __global__ void __launch_bounds__(256)
merge_kernel(float* __restrict__ out)
{
    const int gp = blockIdx.x * 64 + (threadIdx.x >> 2);  // (b,n) pair id
    const int q  = threadIdx.x & 3;
    const int b  = gp >> 8;
    const int n  = gp & 255;
    const float4* base = &g_scratch[(size_t)b * KREC * NN + n];

    float M = -3.4e38f;
    #pragma unroll 4
    for (int i = 0; i < KREC / 4; i++)
        M = fmaxf(M, __ldg(&base[(size_t)(q + 4 * i) * NN]).x);

    float gM = M;
    gM = fmaxf(gM, __shfl_xor_sync(0xffffffffu, gM, 1));
    gM = fmaxf(gM, __shfl_xor_sync(0xffffffffu, gM, 2));

    float S = 0.f, P = 0.f;
    #pragma unroll 4
    for (int i = 0; i < KREC / 4; i++) {
        float4 v = __ldg(&base[(size_t)(q + 4 * i) * NN]);
        float e = __expf(v.x - gM);
        S = fmaf(v.y, e, S);
        P = fmaf(v.z, e, P);
    }
    S += __shfl_xor_sync(0xffffffffu, S, 1);
    P += __shfl_xor_sync(0xffffffffu, P, 1);
    S += __shfl_xor_sync(0xffffffffu, S, 2);
    P += __shfl_xor_sync(0xffffffffu, P, 2);

    if (q == 0)
        out[(size_t)b * NN + n] = P / S;
}

// ---------------------------------------------------------------------------
extern "C" void kernel_launch(void* const* d_in, const int* in_sizes, int n_in,
                              void* d_out, int out_size)
{
    const float* data    = (const float*)d_in[0];   // (64, 256, 64)
    const float* targets = (const float*)d_in[1];   // (64, 256)
    const float* W       = (const float*)d_in[2];   // (4096, 64, 1)
    float* out = (float*)d_out;                     // (64, 256)

    cudaFuncSetAttribute(main_kernel,
                         cudaFuncAttributeMaxDynamicSharedMemorySize,
                         SMEM_BYTES);
    main_kernel<<<dim3(TCH, BB), TPB, SMEM_BYTES>>>(data, targets, W);
    merge_kernel<<<256, 256>>>(out);
}

// round 6
// speedup vs baseline: 2.5149x; 1.1979x over previous
#include <cuda_runtime.h>
#include <cuda_bf16.h>
#include <math.h>
#include <stdint.h>

#define BB 64
#define NN 256
#define DD 64
#define TT 4096
#define T_TILE 256
#define TCH (TT / T_TILE)          // 16
#define THREADS 256
#define WARPS 8
#define NSLAB 32
#define SLABS (NN / NSLAB)         // 8
#define KREC 128                   // 4096 tasks / 32-per-warp

#define DATA_ELTS (BB * NN * DD)   // 1048576
#define W_ELTS (TT * DD)           // 262144

// bf16 limb arrays (hi, mid, lo), row-major d-contiguous
__device__ __align__(16) __nv_bfloat16 g_dlimb[3][DATA_ELTS];
__device__ __align__(16) __nv_bfloat16 g_wlimb[3][W_ELTS];
// per-(b, taskwarp, n) softmax partials: (max, sum_e, sum_e*z, pad). 32 MB.
__device__ float4 g_scratch[(size_t)BB * KREC * NN];

// ---- smem layout ----
#define SM_W   0                       // 3 x (256 rows x 128 B) swizzled
#define SM_D   98304                   // 3 x (256 rows x 128 B) swizzled
#define SM_Z   196608                  // 32 x 260 floats (1040 B rows)
#define ZSTR   260
#define SM_TGT 229888                  // 256 f32
#define SMEM_BYTES 230912

static __device__ __forceinline__ uint32_t smem_u32(const void* p) {
    uint32_t a;
    asm("{ .reg .u64 t; cvta.to.shared.u64 t, %1; cvt.u32.u64 %0, t; }"
        : "=r"(a) : "l"(p));
    return a;
}
static __device__ __forceinline__ void cp16(uint32_t dst, const void* src) {
    asm volatile("cp.async.cg.shared.global [%0], [%1], 16;" :: "r"(dst), "l"(src));
}
#define CP_COMMIT() asm volatile("cp.async.commit_group;")
#define CP_WAIT0()  asm volatile("cp.async.wait_group 0;" ::: "memory")

static __device__ __forceinline__ void ldsm4(uint32_t a, uint32_t r[4]) {
    asm volatile("ldmatrix.sync.aligned.m8n8.x4.shared.b16 {%0,%1,%2,%3}, [%4];"
                 : "=r"(r[0]), "=r"(r[1]), "=r"(r[2]), "=r"(r[3]) : "r"(a));
}
static __device__ __forceinline__ void mma16816(
    float d[4], const uint32_t a[4], uint32_t b0, uint32_t b1) {
    asm volatile(
        "mma.sync.aligned.m16n8k16.row.col.f32.bf16.bf16.f32 "
        "{%0,%1,%2,%3}, {%4,%5,%6,%7}, {%8,%9}, {%0,%1,%2,%3};"
        : "+f"(d[0]), "+f"(d[1]), "+f"(d[2]), "+f"(d[3])
        : "r"(a[0]), "r"(a[1]), "r"(a[2]), "r"(a[3]), "r"(b0), "r"(b1));
}

__device__ __forceinline__ unsigned fkey(float x) {
    unsigned u = __float_as_uint(x);
    return (u & 0x80000000u) ? ~u : (u | 0x80000000u);
}
__device__ __forceinline__ float finv(unsigned k) {
    unsigned u = (k & 0x80000000u) ? (k ^ 0x80000000u) : ~k;
    return __uint_as_float(u);
}

// ---------------------------------------------------------------------------
// Prep: fp32 -> 3 bf16 limbs (hi/mid/lo) for data and W.
// ---------------------------------------------------------------------------
__global__ void __launch_bounds__(256)
prep_kernel(const float* __restrict__ data, const float* __restrict__ W)
{
    size_t i = ((size_t)blockIdx.x * 256 + threadIdx.x) * 2;
    const bool isW = (i >= DATA_ELTS);
    size_t j = isW ? i - DATA_ELTS : i;
    float2 x = isW ? *(const float2*)(W + j) : *(const float2*)(data + j);

    __nv_bfloat16 L[3][2];
    #pragma unroll
    for (int e = 0; e < 2; e++) {
        float v = e ? x.y : x.x;
        __nv_bfloat16 h = __float2bfloat16(v);
        float r1 = v - __bfloat162float(h);
        __nv_bfloat16 m = __float2bfloat16(r1);
        float r2 = r1 - __bfloat162float(m);
        L[0][e] = h; L[1][e] = m; L[2][e] = __float2bfloat16(r2);
    }
    #pragma unroll
    for (int q = 0; q < 3; q++) {
        __nv_bfloat162 pk = __halves2bfloat162(L[q][0], L[q][1]);
        if (isW) *(__nv_bfloat162*)(&g_wlimb[q][j]) = pk;
        else     *(__nv_bfloat162*)(&g_dlimb[q][j]) = pk;
    }
}

// ---------------------------------------------------------------------------
// Main: mma.sync 3-limb GEMM + per-warp cum-scan + softmax partials.
// grid (TCH, BB), 256 threads, 1 CTA/SM.
// ---------------------------------------------------------------------------
extern "C" __global__ void __launch_bounds__(THREADS, 1)
main_kernel(const float* __restrict__ targets)
{
    extern __shared__ __align__(1024) char smem[];
    const uint32_t sb = smem_u32(smem);
    const int tc   = blockIdx.x;
    const int b    = blockIdx.y;
    const int tid  = threadIdx.x;
    const int w    = tid >> 5;
    const int lane = tid & 31;

    // ---- prologue: stage W limbs, data limbs (SW128-swizzled rows), tgt ----
    #pragma unroll
    for (int kq = 0; kq < 24; kq++) {         // W: 3*256*8 = 6144 16B chunks
        int i = kq * THREADS + tid;
        int limb = i >> 11, rem = i & 2047, row = rem >> 3, c = rem & 7;
        cp16(sb + SM_W + limb * 32768 + row * 128 + ((c ^ (row & 7)) << 4),
             &g_wlimb[limb][(size_t)(tc * T_TILE + row) * DD + c * 8]);
    }
    #pragma unroll
    for (int kq = 0; kq < 24; kq++) {         // data: rows are n
        int i = kq * THREADS + tid;
        int limb = i >> 11, rem = i & 2047, row = rem >> 3, c = rem & 7;
        cp16(sb + SM_D + limb * 32768 + row * 128 + ((c ^ (row & 7)) << 4),
             &g_dlimb[limb][((size_t)b * NN + row) * DD + c * 8]);
    }
    if (tid < 64) cp16(sb + SM_TGT + tid * 16, targets + (size_t)b * NN + tid * 4);
    CP_COMMIT();
    CP_WAIT0();
    __syncthreads();

    // fragment lane decomposition
    const int l7 = lane & 7;
    const int t1 = (lane >> 3) & 1;
    const int t2 = lane >> 4;

    // per-k xor'd chunk offsets (A uses t2 as chunk-sel, B uses t1)
    uint32_t xA[4], xB[4];
    #pragma unroll
    for (int k = 0; k < 4; k++) {
        xA[k] = (uint32_t)(((2 * k + t2) ^ l7) << 4);
        xB[k] = (uint32_t)(((2 * k + t1) ^ l7) << 4);
    }
    const uint32_t aRow = sb + SM_W + (uint32_t)(32 * w + 8 * t1 + l7) * 128;
    const uint32_t bRow = sb + SM_D + (uint32_t)(8 * t2 + l7) * 128;

    // limb product pairs: (hh)(hm)(mh)(mm)(hl)(lh)
    const int PA[6] = {0, 0, 1, 1, 0, 2};
    const int PB[6] = {0, 1, 0, 1, 2, 0};

    float* zw = (float*)(smem + SM_Z);
    const float* s_tgt = (const float*)(smem + SM_TGT);

    float cum = 0.f;
    const int gw = tc * WARPS + w;
    float4* srec = &g_scratch[((size_t)b * KREC + gw) * NN];

    for (int s = 0; s < SLABS; s++) {
        // ---- GEMM: 32 tasks x 32 n x k64, 6 limb products ----
        float acc[2][4][4];
        #pragma unroll
        for (int mt = 0; mt < 2; mt++)
            #pragma unroll
            for (int q = 0; q < 4; q++)
                #pragma unroll
                for (int r = 0; r < 4; r++) acc[mt][q][r] = 0.f;

        const uint32_t bSlab = bRow + (uint32_t)(NSLAB * s) * 128;
        #pragma unroll
        for (int p = 0; p < 6; p++) {
            const uint32_t aL = aRow + (uint32_t)PA[p] * 32768;
            const uint32_t bL = bSlab + (uint32_t)PB[p] * 32768;
            #pragma unroll
            for (int k = 0; k < 4; k++) {
                uint32_t a0[4], a1[4], b0[4], b1[4];
                ldsm4(aL + xA[k],        a0);          // tasks 32w..+15
                ldsm4(aL + 2048 + xA[k], a1);          // tasks +16..31
                ldsm4(bL + xB[k],        b0);          // n 0..15 of slab
                ldsm4(bL + 2048 + xB[k], b1);          // n 16..31 of slab
                mma16816(acc[0][0], a0, b0[0], b0[1]);
                mma16816(acc[0][1], a0, b0[2], b0[3]);
                mma16816(acc[0][2], a0, b1[0], b1[1]);
                mma16816(acc[0][3], a0, b1[2], b1[3]);
                mma16816(acc[1][0], a1, b0[0], b0[1]);
                mma16816(acc[1][1], a1, b0[2], b0[3]);
                mma16816(acc[1][2], a1, b1[0], b1[1]);
                mma16816(acc[1][3], a1, b1[2], b1[3]);
            }
        }

        // ---- transpose-store z[n_local][t_local] (stride-260 pad) ----
        {
            const int r0 = lane >> 2;
            const int c0 = 2 * (lane & 3);
            #pragma unroll
            for (int mt = 0; mt < 2; mt++) {
                const int tg = 32 * w + 16 * mt + r0;
                #pragma unroll
                for (int q = 0; q < 4; q++) {
                    const int nl = 8 * q + c0;
                    zw[nl * ZSTR + tg]             = acc[mt][q][0];
                    zw[(nl + 1) * ZSTR + tg]       = acc[mt][q][1];
                    zw[nl * ZSTR + tg + 8]         = acc[mt][q][2];
                    zw[(nl + 1) * ZSTR + tg + 8]   = acc[mt][q][3];
                }
            }
        }
        __syncwarp();

        // ---- epilogue: cum loglik scan + REDUX softmax partials ----
        float mO = 0.f, sO = 0.f, pO = 0.f;
        #pragma unroll
        for (int j = 0; j < NSLAB; j++) {
            float z  = zw[j * ZSTR + tid];
            float tn = s_tgt[s * NSLAB + j];
            float cv = cum;
            float r  = tn - z;
            cum = fmaf(-0.5f * r, r, cum);

            unsigned km = __reduce_max_sync(0xffffffffu, fkey(cv));
            float m = finv(km);
            float e = __expf(cv - m);
            int ie = __float2int_rn(e * 16777216.0f);           // 2^24
            int ip = __float2int_rn(e * z * 131072.0f);         // 2^17
            int se = __reduce_add_sync(0xffffffffu, ie);
            int sp = __reduce_add_sync(0xffffffffu, ip);
            if (lane == j) {
                mO = m;
                sO = (float)se * 5.9604644775390625e-8f;        // 2^-24
                pO = (float)sp * 7.62939453125e-6f;             // 2^-17
            }
        }
        srec[s * NSLAB + lane] = make_float4(mO, sO, pO, 0.f);
        __syncwarp();   // z reads done before next slab's STS
    }
}

// ---------------------------------------------------------------------------
// Merge: 8 threads per (b,n), 16 records each; two-pass stable softmax.
// n==0 falls out naturally (all maxes 0 -> uniform -> pred0).
// ---------------------------------------------------------------------------
extern "C" __global__ void __launch_bounds__(256)
merge_kernel(float* __restrict__ out)
{
    const int gp = blockIdx.x * 32 + (threadIdx.x >> 3);
    const int q  = threadIdx.x & 7;
    const int b  = gp >> 8;
    const int n  = gp & 255;
    const float4* base = &g_scratch[(size_t)b * KREC * NN + n];

    float M = -3.4e38f;
    #pragma unroll 4
    for (int i = 0; i < KREC / 8; i++)
        M = fmaxf(M, __ldg(&base[(size_t)(q + 8 * i) * NN]).x);

    float gM = M;
    gM = fmaxf(gM, __shfl_xor_sync(0xffffffffu, gM, 1));
    gM = fmaxf(gM, __shfl_xor_sync(0xffffffffu, gM, 2));
    gM = fmaxf(gM, __shfl_xor_sync(0xffffffffu, gM, 4));

    float S = 0.f, P = 0.f;
    #pragma unroll 4
    for (int i = 0; i < KREC / 8; i++) {
        float4 v = __ldg(&base[(size_t)(q + 8 * i) * NN]);
        float e = __expf(v.x - gM);
        S = fmaf(v.y, e, S);
        P = fmaf(v.z, e, P);
    }
    S += __shfl_xor_sync(0xffffffffu, S, 1);
    P += __shfl_xor_sync(0xffffffffu, P, 1);
    S += __shfl_xor_sync(0xffffffffu, S, 2);
    P += __shfl_xor_sync(0xffffffffu, P, 2);
    S += __shfl_xor_sync(0xffffffffu, S, 4);
    P += __shfl_xor_sync(0xffffffffu, P, 4);

    if (q == 0)
        out[(size_t)b * NN + n] = P / S;
}

// ---------------------------------------------------------------------------
extern "C" void kernel_launch(void* const* d_in, const int* in_sizes, int n_in,
                              void* d_out, int out_size)
{
    const float* data    = (const float*)d_in[0];   // (64, 256, 64)
    const float* targets = (const float*)d_in[1];   // (64, 256)
    const float* W       = (const float*)d_in[2];   // (4096, 64, 1)
    float* out = (float*)d_out;                     // (64, 256)

    cudaFuncSetAttribute(main_kernel,
                         cudaFuncAttributeMaxDynamicSharedMemorySize,
                         SMEM_BYTES);

    prep_kernel<<<(DATA_ELTS + W_ELTS) / 512, 256>>>(data, W);
    main_kernel<<<dim3(TCH, BB), THREADS, SMEM_BYTES>>>(targets);
    merge_kernel<<<512, 256>>>(out);
}

// round 7
// speedup vs baseline: 3.5252x; 1.4017x over previous
#include <cuda_runtime.h>
#include <cuda_bf16.h>
#include <math.h>
#include <stdint.h>

#define BB 64
#define NN 256
#define DD 64
#define TT 4096
#define T_TILE 256
#define TCH (TT / T_TILE)          // 16
#define THREADS 256
#define WARPS 8
#define NSLAB 32
#define SLABS (NN / NSLAB)         // 8
#define KREC 128                   // 4096 tasks / 32-per-warp

#define DATA_ELTS (BB * NN * DD)   // 1048576
#define W_ELTS (TT * DD)           // 262144

// bf16 limb arrays (hi, mid), row-major d-contiguous
__device__ __align__(16) __nv_bfloat16 g_dlimb[2][DATA_ELTS];
__device__ __align__(16) __nv_bfloat16 g_wlimb[2][W_ELTS];
// per-(b, taskwarp, n) softmax partials: (max, sum_e, sum_e*z, pad). 32 MB.
__device__ float4 g_scratch[(size_t)BB * KREC * NN];

// ---- smem layout ----
#define SM_W   0                       // 2 x (256 rows x 128 B) swizzled
#define SM_D   65536                   // 2 x (256 rows x 128 B) swizzled
#define SM_Z   131072                  // 32 x 260 floats
#define ZSTR   260
#define SM_TGT 164352                  // 256 f32
#define SMEM_BYTES 165376

static __device__ __forceinline__ uint32_t smem_u32(const void* p) {
    uint32_t a;
    asm("{ .reg .u64 t; cvta.to.shared.u64 t, %1; cvt.u32.u64 %0, t; }"
        : "=r"(a) : "l"(p));
    return a;
}
static __device__ __forceinline__ void cp16(uint32_t dst, const void* src) {
    asm volatile("cp.async.cg.shared.global [%0], [%1], 16;" :: "r"(dst), "l"(src));
}
#define CP_COMMIT() asm volatile("cp.async.commit_group;")
#define CP_WAIT0()  asm volatile("cp.async.wait_group 0;" ::: "memory")

static __device__ __forceinline__ void ldsm4(uint32_t a, uint32_t r[4]) {
    asm volatile("ldmatrix.sync.aligned.m8n8.x4.shared.b16 {%0,%1,%2,%3}, [%4];"
                 : "=r"(r[0]), "=r"(r[1]), "=r"(r[2]), "=r"(r[3]) : "r"(a));
}
static __device__ __forceinline__ void mma16816(
    float d[4], const uint32_t a[4], uint32_t b0, uint32_t b1) {
    asm volatile(
        "mma.sync.aligned.m16n8k16.row.col.f32.bf16.bf16.f32 "
        "{%0,%1,%2,%3}, {%4,%5,%6,%7}, {%8,%9}, {%0,%1,%2,%3};"
        : "+f"(d[0]), "+f"(d[1]), "+f"(d[2]), "+f"(d[3])
        : "r"(a[0]), "r"(a[1]), "r"(a[2]), "r"(a[3]), "r"(b0), "r"(b1));
}

__device__ __forceinline__ unsigned fkey(float x) {
    unsigned u = __float_as_uint(x);
    return (u & 0x80000000u) ? ~u : (u | 0x80000000u);
}
__device__ __forceinline__ float finv(unsigned k) {
    unsigned u = (k & 0x80000000u) ? (k ^ 0x80000000u) : ~k;
    return __uint_as_float(u);
}

// ---------------------------------------------------------------------------
// Prep: fp32 -> 2 bf16 limbs (hi/mid) for data and W.
// ---------------------------------------------------------------------------
__global__ void __launch_bounds__(256)
prep_kernel(const float* __restrict__ data, const float* __restrict__ W)
{
    size_t i = ((size_t)blockIdx.x * 256 + threadIdx.x) * 2;
    const bool isW = (i >= DATA_ELTS);
    size_t j = isW ? i - DATA_ELTS : i;
    float2 x = isW ? *(const float2*)(W + j) : *(const float2*)(data + j);

    __nv_bfloat16 L[2][2];
    #pragma unroll
    for (int e = 0; e < 2; e++) {
        float v = e ? x.y : x.x;
        __nv_bfloat16 h = __float2bfloat16(v);
        L[0][e] = h;
        L[1][e] = __float2bfloat16(v - __bfloat162float(h));
    }
    #pragma unroll
    for (int q = 0; q < 2; q++) {
        __nv_bfloat162 pk = __halves2bfloat162(L[q][0], L[q][1]);
        if (isW) *(__nv_bfloat162*)(&g_wlimb[q][j]) = pk;
        else     *(__nv_bfloat162*)(&g_dlimb[q][j]) = pk;
    }
}

// ---------------------------------------------------------------------------
// Main: mma.sync 2-limb (3-product) GEMM + per-warp cum-scan + partials.
// grid (TCH, BB), 256 threads, 1 CTA/SM.
// ---------------------------------------------------------------------------
extern "C" __global__ void __launch_bounds__(THREADS, 1)
main_kernel(const float* __restrict__ targets)
{
    extern __shared__ __align__(1024) char smem[];
    const uint32_t sb = smem_u32(smem);
    const int tc   = blockIdx.x;
    const int b    = blockIdx.y;
    const int tid  = threadIdx.x;
    const int w    = tid >> 5;
    const int lane = tid & 31;

    // ---- prologue: stage W limbs, data limbs (swizzled rows), targets ----
    #pragma unroll
    for (int kq = 0; kq < 16; kq++) {         // W: 2*256*8 = 4096 16B chunks
        int i = kq * THREADS + tid;
        int limb = i >> 11, rem = i & 2047, row = rem >> 3, c = rem & 7;
        cp16(sb + SM_W + limb * 32768 + row * 128 + ((c ^ (row & 7)) << 4),
             &g_wlimb[limb][(size_t)(tc * T_TILE + row) * DD + c * 8]);
    }
    #pragma unroll
    for (int kq = 0; kq < 16; kq++) {         // data: rows are n
        int i = kq * THREADS + tid;
        int limb = i >> 11, rem = i & 2047, row = rem >> 3, c = rem & 7;
        cp16(sb + SM_D + limb * 32768 + row * 128 + ((c ^ (row & 7)) << 4),
             &g_dlimb[limb][((size_t)b * NN + row) * DD + c * 8]);
    }
    if (tid < 64) cp16(sb + SM_TGT + tid * 16, targets + (size_t)b * NN + tid * 4);
    CP_COMMIT();
    CP_WAIT0();
    __syncthreads();

    // fragment lane decomposition
    const int l7 = lane & 7;
    const int t1 = (lane >> 3) & 1;
    const int t2 = lane >> 4;

    uint32_t xA[4], xB[4];
    #pragma unroll
    for (int k = 0; k < 4; k++) {
        xA[k] = (uint32_t)(((2 * k + t2) ^ l7) << 4);
        xB[k] = (uint32_t)(((2 * k + t1) ^ l7) << 4);
    }
    const uint32_t aRow = sb + SM_W + (uint32_t)(32 * w + 8 * t1 + l7) * 128;
    const uint32_t bRow = sb + SM_D + (uint32_t)(8 * t2 + l7) * 128;

    // limb product pairs: (hh)(hm)(mh)
    const int PA[3] = {0, 0, 1};
    const int PB[3] = {0, 1, 0};

    float* zw = (float*)(smem + SM_Z);
    const float* s_tgt = (const float*)(smem + SM_TGT);

    float cum = 0.f;
    const int gw = tc * WARPS + w;
    float4* srec = &g_scratch[((size_t)b * KREC + gw) * NN];

    for (int s = 0; s < SLABS; s++) {
        // ---- GEMM: 32 tasks x 32 n x k64, 3 limb products ----
        float acc[2][4][4];
        #pragma unroll
        for (int mt = 0; mt < 2; mt++)
            #pragma unroll
            for (int q = 0; q < 4; q++)
                #pragma unroll
                for (int r = 0; r < 4; r++) acc[mt][q][r] = 0.f;

        const uint32_t bSlab = bRow + (uint32_t)(NSLAB * s) * 128;
        #pragma unroll
        for (int p = 0; p < 3; p++) {
            const uint32_t aL = aRow + (uint32_t)PA[p] * 32768;
            const uint32_t bL = bSlab + (uint32_t)PB[p] * 32768;
            #pragma unroll
            for (int k = 0; k < 4; k++) {
                uint32_t a0[4], a1[4], b0[4], b1[4];
                ldsm4(aL + xA[k],        a0);
                ldsm4(aL + 2048 + xA[k], a1);
                ldsm4(bL + xB[k],        b0);
                ldsm4(bL + 2048 + xB[k], b1);
                mma16816(acc[0][0], a0, b0[0], b0[1]);
                mma16816(acc[0][1], a0, b0[2], b0[3]);
                mma16816(acc[0][2], a0, b1[0], b1[1]);
                mma16816(acc[0][3], a0, b1[2], b1[3]);
                mma16816(acc[1][0], a1, b0[0], b0[1]);
                mma16816(acc[1][1], a1, b0[2], b0[3]);
                mma16816(acc[1][2], a1, b1[0], b1[1]);
                mma16816(acc[1][3], a1, b1[2], b1[3]);
            }
        }

        // ---- transpose-store z[n_local][t_local] ----
        {
            const int r0 = lane >> 2;
            const int c0 = 2 * (lane & 3);
            #pragma unroll
            for (int mt = 0; mt < 2; mt++) {
                const int tg = 32 * w + 16 * mt + r0;
                #pragma unroll
                for (int q = 0; q < 4; q++) {
                    const int nl = 8 * q + c0;
                    zw[nl * ZSTR + tg]           = acc[mt][q][0];
                    zw[(nl + 1) * ZSTR + tg]     = acc[mt][q][1];
                    zw[nl * ZSTR + tg + 8]       = acc[mt][q][2];
                    zw[(nl + 1) * ZSTR + tg + 8] = acc[mt][q][3];
                }
            }
        }
        __syncwarp();

        // ---- epilogue: cum loglik scan + REDUX softmax partials ----
        float mO = 0.f, sO = 0.f, pO = 0.f;
        #pragma unroll
        for (int j = 0; j < NSLAB; j++) {
            float z  = zw[j * ZSTR + tid];
            float tn = s_tgt[s * NSLAB + j];
            float cv = cum;
            float r  = tn - z;
            cum = fmaf(-0.5f * r, r, cum);

            unsigned km = __reduce_max_sync(0xffffffffu, fkey(cv));
            float m = finv(km);
            float e = __expf(cv - m);
            int ie = __float2int_rn(e * 16777216.0f);           // 2^24
            int ip = __float2int_rn(e * z * 131072.0f);         // 2^17
            int se = __reduce_add_sync(0xffffffffu, ie);
            int sp = __reduce_add_sync(0xffffffffu, ip);
            if (lane == j) {
                mO = m;
                sO = (float)se * 5.9604644775390625e-8f;        // 2^-24
                pO = (float)sp * 7.62939453125e-6f;             // 2^-17
            }
        }
        srec[s * NSLAB + lane] = make_float4(mO, sO, pO, 0.f);
        __syncwarp();
    }
}

// ---------------------------------------------------------------------------
// Merge: 8 threads per (b,n), 16 records each; two-pass stable softmax.
// n==0 falls out naturally (all maxes 0 -> uniform -> pred0).
// ---------------------------------------------------------------------------
extern "C" __global__ void __launch_bounds__(256)
merge_kernel(float* __restrict__ out)
{
    const int gp = blockIdx.x * 32 + (threadIdx.x >> 3);
    const int q  = threadIdx.x & 7;
    const int b  = gp >> 8;
    const int n  = gp & 255;
    const float4* base = &g_scratch[(size_t)b * KREC * NN + n];

    float M = -3.4e38f;
    #pragma unroll 4
    for (int i = 0; i < KREC / 8; i++)
        M = fmaxf(M, __ldg(&base[(size_t)(q + 8 * i) * NN]).x);

    float gM = M;
    gM = fmaxf(gM, __shfl_xor_sync(0xffffffffu, gM, 1));
    gM = fmaxf(gM, __shfl_xor_sync(0xffffffffu, gM, 2));
    gM = fmaxf(gM, __shfl_xor_sync(0xffffffffu, gM, 4));

    float S = 0.f, P = 0.f;
    #pragma unroll 4
    for (int i = 0; i < KREC / 8; i++) {
        float4 v = __ldg(&base[(size_t)(q + 8 * i) * NN]);
        float e = __expf(v.x - gM);
        S = fmaf(v.y, e, S);
        P = fmaf(v.z, e, P);
    }
    S += __shfl_xor_sync(0xffffffffu, S, 1);
    P += __shfl_xor_sync(0xffffffffu, P, 1);
    S += __shfl_xor_sync(0xffffffffu, S, 2);
    P += __shfl_xor_sync(0xffffffffu, P, 2);
    S += __shfl_xor_sync(0xffffffffu, S, 4);
    P += __shfl_xor_sync(0xffffffffu, P, 4);

    if (q == 0)
        out[(size_t)b * NN + n] = P / S;
}

// ---------------------------------------------------------------------------
extern "C" void kernel_launch(void* const* d_in, const int* in_sizes, int n_in,
                              void* d_out, int out_size)
{
    const float* data    = (const float*)d_in[0];   // (64, 256, 64)
    const float* targets = (const float*)d_in[1];   // (64, 256)
    const float* W       = (const float*)d_in[2];   // (4096, 64, 1)
    float* out = (float*)d_out;                     // (64, 256)

    cudaFuncSetAttribute(main_kernel,
                         cudaFuncAttributeMaxDynamicSharedMemorySize,
                         SMEM_BYTES);

    prep_kernel<<<(DATA_ELTS + W_ELTS) / 512, 256>>>(data, W);
    main_kernel<<<dim3(TCH, BB), THREADS, SMEM_BYTES>>>(targets);
    merge_kernel<<<512, 256>>>(out);
}